// round 1
// baseline (speedup 1.0000x reference)
#include <cuda_runtime.h>
#include <cstdint>

#define BATCH 16
#define CDIM 384
#define QCDIM 192
#define HWDIM 4096
#define HEADS 8
#define DCH 48
#define ZROWS 576  // 384 x-channels + 192 query-channels

// ---------------- scratch (device globals; no allocation allowed) ----------------
__device__ float g_G[BATCH * ZROWS * ZROWS];    // per-batch Gram of Z=[X;Q]
__device__ float g_T1[BATCH * CDIM * CDIM];     // W_k @ G_x
__device__ float g_V1[BATCH * CDIM * CDIM];     // W_q @ G_qx
__device__ float g_T2[BATCH * CDIM * QCDIM];    // W_q @ G_q
__device__ float g_nk[BATCH * CDIM];            // ||k_row||^2
__device__ float g_nq[BATCH * CDIM];            // ||q_row||^2
__device__ float g_Av[BATCH * CDIM * CDIM];     // blockdiag(attn) @ W_v
__device__ float g_M[BATCH * CDIM * CDIM];      // W_proj @ Av

// ---------------- helpers ----------------
__device__ __forceinline__ uint32_t f2tf32(float f) {
  uint32_t u;
  asm("cvt.rna.tf32.f32 %0, %1;" : "=r"(u) : "f"(f));
  return u;
}

__device__ __forceinline__ void mma_tf32(float c[4], const uint32_t a[4],
                                         const uint32_t b[2]) {
  asm volatile(
      "mma.sync.aligned.m16n8k8.row.col.f32.tf32.tf32.f32 "
      "{%0,%1,%2,%3}, {%4,%5,%6,%7}, {%8,%9}, {%0,%1,%2,%3};\n"
      : "+f"(c[0]), "+f"(c[1]), "+f"(c[2]), "+f"(c[3])
      : "r"(a[0]), "r"(a[1]), "r"(a[2]), "r"(a[3]), "r"(b[0]), "r"(b[1]));
}

// ---------------- kernel 1: Gram  G_b = Z_b Z_b^T (tf32 MMA, NT, symmetric) ----------------
// grid: (15 upper-tri tile pairs of 5x5, batch), block 256
__global__ __launch_bounds__(256) void gram_nt_kernel(
    const float* __restrict__ x, const float* __restrict__ query,
    float* __restrict__ G) {
  const int b = blockIdx.y;
  const int t = blockIdx.x;
  int ti = 0, tj = 0;
  {
    int accn = 0;
#pragma unroll
    for (int r = 0; r < 5; r++) {
      int cnt = 5 - r;
      if (t >= accn && t < accn + cnt) { ti = r; tj = r + (t - accn); }
      accn += cnt;
    }
  }
  const int i0 = ti * 128, j0 = tj * 128;

  __shared__ uint32_t As[128][36];  // pad 36 -> conflict-free frag reads
  __shared__ uint32_t Bs[128][36];

  const float* xb = x + (size_t)b * CDIM * HWDIM;
  const float* qb = query + (size_t)b * QCDIM * HWDIM;

  const int tid = threadIdx.x;
  const int lane = tid & 31, wid = tid >> 5;
  const int wm = wid & 1, wn = wid >> 1;  // warp tile: 64 rows x 32 cols
  const int g = lane >> 2, tg = lane & 3;

  float acc[4][4][4];
#pragma unroll
  for (int a = 0; a < 4; a++)
#pragma unroll
    for (int bb = 0; bb < 4; bb++)
#pragma unroll
      for (int cc = 0; cc < 4; cc++) acc[a][bb][cc] = 0.f;

  for (int kt = 0; kt < HWDIM; kt += 32) {
#pragma unroll
    for (int i = 0; i < 4; i++) {
      int idx = tid + i * 256;
      int r = idx >> 3, c4 = idx & 7;
      {  // A stripe rows i0..i0+127
        int row = i0 + r;
        float4 v = make_float4(0.f, 0.f, 0.f, 0.f);
        if (row < ZROWS) {
          const float* p = (row < CDIM) ? (xb + (size_t)row * HWDIM)
                                        : (qb + (size_t)(row - CDIM) * HWDIM);
          v = *reinterpret_cast<const float4*>(p + kt + c4 * 4);
        }
        As[r][c4 * 4 + 0] = f2tf32(v.x);
        As[r][c4 * 4 + 1] = f2tf32(v.y);
        As[r][c4 * 4 + 2] = f2tf32(v.z);
        As[r][c4 * 4 + 3] = f2tf32(v.w);
      }
      {  // B stripe rows j0..j0+127
        int row = j0 + r;
        float4 v = make_float4(0.f, 0.f, 0.f, 0.f);
        if (row < ZROWS) {
          const float* p = (row < CDIM) ? (xb + (size_t)row * HWDIM)
                                        : (qb + (size_t)(row - CDIM) * HWDIM);
          v = *reinterpret_cast<const float4*>(p + kt + c4 * 4);
        }
        Bs[r][c4 * 4 + 0] = f2tf32(v.x);
        Bs[r][c4 * 4 + 1] = f2tf32(v.y);
        Bs[r][c4 * 4 + 2] = f2tf32(v.z);
        Bs[r][c4 * 4 + 3] = f2tf32(v.w);
      }
    }
    __syncthreads();
#pragma unroll
    for (int kk = 0; kk < 32; kk += 8) {
      uint32_t af[4][4], bf[4][2];
#pragma unroll
      for (int mf = 0; mf < 4; mf++) {
        int r = wm * 64 + mf * 16;
        af[mf][0] = As[r + g][kk + tg];
        af[mf][1] = As[r + g + 8][kk + tg];
        af[mf][2] = As[r + g][kk + tg + 4];
        af[mf][3] = As[r + g + 8][kk + tg + 4];
      }
#pragma unroll
      for (int nf = 0; nf < 4; nf++) {
        int rn = wn * 32 + nf * 8;
        bf[nf][0] = Bs[rn + g][kk + tg];
        bf[nf][1] = Bs[rn + g][kk + tg + 4];
      }
#pragma unroll
      for (int mf = 0; mf < 4; mf++)
#pragma unroll
        for (int nf = 0; nf < 4; nf++) mma_tf32(acc[mf][nf], af[mf], bf[nf]);
    }
    __syncthreads();
  }

  float* Gb = G + (size_t)b * ZROWS * ZROWS;
#pragma unroll
  for (int mf = 0; mf < 4; mf++)
#pragma unroll
    for (int nf = 0; nf < 4; nf++) {
      int ib = i0 + wm * 64 + mf * 16 + g;
      int jb = j0 + wn * 32 + nf * 8 + 2 * tg;
#pragma unroll
      for (int e = 0; e < 4; e++) {
        int ii = ib + ((e >= 2) ? 8 : 0);
        int jj = jb + (e & 1);
        float v = acc[mf][nf][e];
        if (ii < ZROWS && jj < ZROWS) {
          Gb[(size_t)ii * ZROWS + jj] = v;
          Gb[(size_t)jj * ZROWS + ii] = v;  // symmetric fill
        }
      }
    }
}

// ---------------- kernel 2: generic NN GEMM (tf32 MMA), C[M,N]=A[M,K]@B[K,N] ----------------
// row-major A,B,C; batch via strides; K must be a multiple of 32; N%4==0
__global__ __launch_bounds__(256) void gemm_nn_tf32(
    const float* __restrict__ A, int lda, long long sA,
    const float* __restrict__ B, int ldb, long long sB, float* __restrict__ C,
    int ldc, long long sC, int M, int N, int K) {
  const int b = blockIdx.z;
  A += (size_t)b * sA;
  B += (size_t)b * sB;
  C += (size_t)b * sC;
  const int m0 = blockIdx.y * 128, n0 = blockIdx.x * 128;

  __shared__ uint32_t As[128][36];
  __shared__ uint32_t Bs[32][132];

  const int tid = threadIdx.x;
  const int lane = tid & 31, wid = tid >> 5;
  const int wm = wid & 1, wn = wid >> 1;
  const int g = lane >> 2, tg = lane & 3;

  float acc[4][4][4];
#pragma unroll
  for (int a = 0; a < 4; a++)
#pragma unroll
    for (int bb = 0; bb < 4; bb++)
#pragma unroll
      for (int cc = 0; cc < 4; cc++) acc[a][bb][cc] = 0.f;

  for (int kt = 0; kt < K; kt += 32) {
#pragma unroll
    for (int i = 0; i < 4; i++) {
      int idx = tid + i * 256;
      {  // A tile: 128 rows x 32 cols
        int r = idx >> 3, c4 = idx & 7;
        int row = m0 + r;
        float4 v = make_float4(0.f, 0.f, 0.f, 0.f);
        if (row < M)
          v = *reinterpret_cast<const float4*>(A + (size_t)row * lda + kt + c4 * 4);
        As[r][c4 * 4 + 0] = f2tf32(v.x);
        As[r][c4 * 4 + 1] = f2tf32(v.y);
        As[r][c4 * 4 + 2] = f2tf32(v.z);
        As[r][c4 * 4 + 3] = f2tf32(v.w);
      }
      {  // B tile: 32 rows (k) x 128 cols (n)
        int r = idx >> 5, c4 = idx & 31;
        int col = n0 + c4 * 4;
        float4 v = make_float4(0.f, 0.f, 0.f, 0.f);
        if (col < N)
          v = *reinterpret_cast<const float4*>(B + (size_t)(kt + r) * ldb + col);
        Bs[r][c4 * 4 + 0] = f2tf32(v.x);
        Bs[r][c4 * 4 + 1] = f2tf32(v.y);
        Bs[r][c4 * 4 + 2] = f2tf32(v.z);
        Bs[r][c4 * 4 + 3] = f2tf32(v.w);
      }
    }
    __syncthreads();
#pragma unroll
    for (int kk = 0; kk < 32; kk += 8) {
      uint32_t af[4][4], bf[4][2];
#pragma unroll
      for (int mf = 0; mf < 4; mf++) {
        int r = wm * 64 + mf * 16;
        af[mf][0] = As[r + g][kk + tg];
        af[mf][1] = As[r + g + 8][kk + tg];
        af[mf][2] = As[r + g][kk + tg + 4];
        af[mf][3] = As[r + g + 8][kk + tg + 4];
      }
#pragma unroll
      for (int nf = 0; nf < 4; nf++) {
        int cn = wn * 32 + nf * 8 + g;
        bf[nf][0] = Bs[kk + tg][cn];
        bf[nf][1] = Bs[kk + tg + 4][cn];
      }
#pragma unroll
      for (int mf = 0; mf < 4; mf++)
#pragma unroll
        for (int nf = 0; nf < 4; nf++) mma_tf32(acc[mf][nf], af[mf], bf[nf]);
    }
    __syncthreads();
  }

#pragma unroll
  for (int mf = 0; mf < 4; mf++)
#pragma unroll
    for (int nf = 0; nf < 4; nf++) {
      int ib = m0 + wm * 64 + mf * 16 + g;
      int jb = n0 + wn * 32 + nf * 8 + 2 * tg;
#pragma unroll
      for (int e = 0; e < 4; e++) {
        int ii = ib + ((e >= 2) ? 8 : 0);
        int jj = jb + (e & 1);
        if (ii < M && jj < N) C[(size_t)ii * ldc + jj] = acc[mf][nf][e];
      }
    }
}

// ---------------- kernel 3: row norms  nk = diag(Wk G_x Wk^T), nq = diag(Wq G_q Wq^T) ----------------
// grid (384, 16), block 64
__global__ __launch_bounds__(64) void norms_kernel(
    const float* __restrict__ w_kv, const float* __restrict__ w_q,
    const float* __restrict__ T1, const float* __restrict__ T2,
    float* __restrict__ nk, float* __restrict__ nq) {
  const int o = blockIdx.x;
  const int b = blockIdx.y;
  const int tid = threadIdx.x;
  const int lane = tid & 31, wid = tid >> 5;

  float sk = 0.f, sq = 0.f;
  const float* t1 = T1 + ((size_t)b * CDIM + o) * CDIM;
  const float* wk = w_kv + (size_t)o * CDIM;
  for (int i = tid; i < CDIM; i += 64) sk += t1[i] * wk[i];
  const float* t2 = T2 + ((size_t)b * CDIM + o) * QCDIM;
  const float* wq = w_q + (size_t)o * QCDIM;
  for (int i = tid; i < QCDIM; i += 64) sq += t2[i] * wq[i];

#pragma unroll
  for (int off = 16; off; off >>= 1) {
    sk += __shfl_xor_sync(0xFFFFFFFFu, sk, off);
    sq += __shfl_xor_sync(0xFFFFFFFFu, sq, off);
  }
  __shared__ float s0[2], s1[2];
  if (lane == 0) { s0[wid] = sk; s1[wid] = sq; }
  __syncthreads();
  if (tid == 0) {
    nk[(size_t)b * CDIM + o] = s0[0] + s0[1];
    nq[(size_t)b * CDIM + o] = s1[0] + s1[1];
  }
}

// ---------------- kernel 4: S = V1 Wk^T (per head block) -> softmax -> Av = attn @ Wv ----------------
// grid (8 heads, 16 batch), block 256, dyn smem = 2*48*385*4 bytes
__global__ __launch_bounds__(256) void attn_kernel(
    const float* __restrict__ V1, const float* __restrict__ w_kv,
    const float* __restrict__ nk, const float* __restrict__ nq,
    const float* __restrict__ temperature, float* __restrict__ Av) {
  const int h = blockIdx.x;
  const int b = blockIdx.y;
  extern __shared__ float sm[];
  float* V1h = sm;              // [48][385]
  float* Wh = sm + 48 * 385;    // [48][385]
  __shared__ float Ssm[DCH][DCH + 1];

  const int tid = threadIdx.x;
  const int lane = tid & 31, wid = tid >> 5;

  for (int idx = tid; idx < DCH * CDIM; idx += 256) {
    int c = idx / CDIM, k = idx % CDIM;
    V1h[c * 385 + k] = V1[((size_t)b * CDIM + h * DCH + c) * CDIM + k];
    Wh[c * 385 + k] = w_kv[(size_t)(h * DCH + c) * CDIM + k];  // Wk rows
  }
  __syncthreads();

  const float temp = temperature[h];
  for (int p = tid; p < DCH * DCH; p += 256) {
    int c = p / DCH, d = p % DCH;
    const float* a = &V1h[c * 385];
    const float* w = &Wh[d * 385];
    float s = 0.f;
#pragma unroll 8
    for (int k = 0; k < CDIM; k++) s += a[k] * w[k];
    float dq = fmaxf(sqrtf(fmaxf(nq[(size_t)b * CDIM + h * DCH + c], 0.f)), 1e-12f);
    float dk = fmaxf(sqrtf(fmaxf(nk[(size_t)b * CDIM + h * DCH + d], 0.f)), 1e-12f);
    Ssm[c][d] = s / (dq * dk) * temp;
  }
  __syncthreads();

  // softmax over d (48) per row c; warp per row
  for (int c = wid; c < DCH; c += 8) {
    float a1 = Ssm[c][lane < DCH ? lane : 0];
    float a2 = (lane < DCH - 32) ? Ssm[c][lane + 32] : -1e30f;
    if (lane >= DCH) a1 = -1e30f;
    float m = fmaxf(a1, a2);
#pragma unroll
    for (int off = 16; off; off >>= 1) m = fmaxf(m, __shfl_xor_sync(0xFFFFFFFFu, m, off));
    float e1 = (lane < DCH) ? expf(a1 - m) : 0.f;
    float e2 = (lane < DCH - 32) ? expf(a2 - m) : 0.f;
    float su = e1 + e2;
#pragma unroll
    for (int off = 16; off; off >>= 1) su += __shfl_xor_sync(0xFFFFFFFFu, su, off);
    float inv = 1.f / su;
    if (lane < DCH) Ssm[c][lane] = e1 * inv;
    if (lane < DCH - 32) Ssm[c][lane + 32] = e2 * inv;
  }
  __syncthreads();

  // reuse V1h region for Wv rows of this head
  for (int idx = tid; idx < DCH * CDIM; idx += 256) {
    int d = idx / CDIM, k = idx % CDIM;
    V1h[d * 385 + k] = w_kv[(size_t)(CDIM + h * DCH + d) * CDIM + k];
  }
  __syncthreads();

  for (int idx = tid; idx < DCH * CDIM; idx += 256) {
    int c = idx / CDIM, j = idx % CDIM;
    float a = 0.f;
#pragma unroll 8
    for (int d = 0; d < DCH; d++) a += Ssm[c][d] * V1h[d * 385 + j];
    Av[((size_t)b * CDIM + h * DCH + c) * CDIM + j] = a;
  }
}

// ---------------- host ----------------
extern "C" void kernel_launch(void* const* d_in, const int* in_sizes, int n_in,
                              void* d_out, int out_size) {
  (void)in_sizes; (void)n_in; (void)out_size;
  const float* x = (const float*)d_in[0];
  const float* query = (const float*)d_in[1];
  const float* w_kv = (const float*)d_in[2];
  const float* w_q = (const float*)d_in[3];
  const float* w_proj = (const float*)d_in[4];
  const float* temp = (const float*)d_in[5];
  float* out = (float*)d_out;

  float *G, *T1, *V1, *T2, *nk, *nq, *Av, *M;
  cudaGetSymbolAddress((void**)&G, g_G);
  cudaGetSymbolAddress((void**)&T1, g_T1);
  cudaGetSymbolAddress((void**)&V1, g_V1);
  cudaGetSymbolAddress((void**)&T2, g_T2);
  cudaGetSymbolAddress((void**)&nk, g_nk);
  cudaGetSymbolAddress((void**)&nq, g_nq);
  cudaGetSymbolAddress((void**)&Av, g_Av);
  cudaGetSymbolAddress((void**)&M, g_M);

  // 1) Gram: G_b = Z Z^T   (Z = [X; Q], 576 x 4096)
  gram_nt_kernel<<<dim3(15, BATCH), 256>>>(x, query, G);

  // 2) T1 = W_k @ G_x     [384x384] = [384x384]@[384x384]
  gemm_nn_tf32<<<dim3(3, 3, BATCH), 256>>>(
      w_kv, CDIM, 0LL, G, ZROWS, (long long)ZROWS * ZROWS, T1, CDIM,
      (long long)CDIM * CDIM, CDIM, CDIM, CDIM);
  // 3) V1 = W_q @ G_qx    [384x384] = [384x192]@[192x384]
  gemm_nn_tf32<<<dim3(3, 3, BATCH), 256>>>(
      w_q, QCDIM, 0LL, G + (size_t)CDIM * ZROWS, ZROWS,
      (long long)ZROWS * ZROWS, V1, CDIM, (long long)CDIM * CDIM, CDIM, CDIM,
      QCDIM);
  // 4) T2 = W_q @ G_q     [384x192] = [384x192]@[192x192]
  gemm_nn_tf32<<<dim3(2, 3, BATCH), 256>>>(
      w_q, QCDIM, 0LL, G + (size_t)CDIM * ZROWS + CDIM, ZROWS,
      (long long)ZROWS * ZROWS, T2, QCDIM, (long long)CDIM * QCDIM, CDIM,
      QCDIM, QCDIM);

  // 5) norms
  norms_kernel<<<dim3(CDIM, BATCH), 64>>>(w_kv, w_q, T1, T2, nk, nq);

  // 6) logits + softmax + Av  (dyn smem 148 KB)
  const int attn_smem = 2 * 48 * 385 * (int)sizeof(float);
  cudaFuncSetAttribute(attn_kernel, cudaFuncAttributeMaxDynamicSharedMemorySize,
                       attn_smem);
  attn_kernel<<<dim3(HEADS, BATCH), 256, attn_smem>>>(V1, w_kv, nk, nq, temp, Av);

  // 7) M = W_proj @ Av    [384x384]
  gemm_nn_tf32<<<dim3(3, 3, BATCH), 256>>>(
      w_proj, CDIM, 0LL, Av, CDIM, (long long)CDIM * CDIM, M, CDIM,
      (long long)CDIM * CDIM, CDIM, CDIM, CDIM);

  // 8) out = M @ X        [384x4096] per batch
  gemm_nn_tf32<<<dim3(32, 3, BATCH), 256>>>(
      M, CDIM, (long long)CDIM * CDIM, x, HWDIM, (long long)CDIM * HWDIM, out,
      HWDIM, (long long)CDIM * HWDIM, CDIM, HWDIM, CDIM);
}

// round 3
// speedup vs baseline: 1.0830x; 1.0830x over previous
#include <cuda_runtime.h>
#include <cstdint>

#define BATCH 16
#define CDIM 384
#define QCDIM 192
#define HWDIM 4096
#define HEADS 8
#define DCH 48
#define ZROWS 576  // 384 x-channels + 192 query-channels

// ---------------- scratch ----------------
__device__ float g_G[BATCH * ZROWS * ZROWS];
__device__ float g_T1[BATCH * CDIM * CDIM];
__device__ float g_V1[BATCH * CDIM * CDIM];
__device__ float g_T2[BATCH * CDIM * QCDIM];
__device__ float g_Av[BATCH * CDIM * CDIM];
__device__ float g_M[BATCH * CDIM * CDIM];

// ---------------- helpers ----------------
__device__ __forceinline__ uint32_t f2tf32(float f) {
  uint32_t u;
  asm("cvt.rna.tf32.f32 %0, %1;" : "=r"(u) : "f"(f));
  return u;
}

__device__ __forceinline__ void mma_tf32(float c[4], const uint32_t a[4],
                                         const uint32_t b[2]) {
  asm volatile(
      "mma.sync.aligned.m16n8k8.row.col.f32.tf32.tf32.f32 "
      "{%0,%1,%2,%3}, {%4,%5,%6,%7}, {%8,%9}, {%0,%1,%2,%3};\n"
      : "+f"(c[0]), "+f"(c[1]), "+f"(c[2]), "+f"(c[3])
      : "r"(a[0]), "r"(a[1]), "r"(a[2]), "r"(a[3]), "r"(b[0]), "r"(b[1]));
}

// =====================================================================
// kernel 1: Gram  G_b = Z_b Z_b^T  (tf32, NT, symmetric, double-buffered)
// grid (15, 16), block 256, dyn smem = 2*(128*36)*2*4 = 73728 B
// =====================================================================
__global__ __launch_bounds__(256) void gram_nt_kernel(
    const float* __restrict__ x, const float* __restrict__ query,
    float* __restrict__ G) {
  extern __shared__ uint32_t smg[];
  uint32_t* As = smg;                  // [2][128][36]
  uint32_t* Bs = smg + 2 * 128 * 36;   // [2][128][36]

  const int b = blockIdx.y;
  const int t = blockIdx.x;
  int ti = 0, tj = 0;
  {
    int accn = 0;
#pragma unroll
    for (int r = 0; r < 5; r++) {
      int cnt = 5 - r;
      if (t >= accn && t < accn + cnt) { ti = r; tj = r + (t - accn); }
      accn += cnt;
    }
  }
  const int i0 = ti * 128, j0 = tj * 128;

  const float* xb = x + (size_t)b * CDIM * HWDIM;
  const float* qb = query + (size_t)b * QCDIM * HWDIM;

  const int tid = threadIdx.x;
  const int lane = tid & 31, wid = tid >> 5;
  const int wm = wid & 1, wn = wid >> 1;
  const int g = lane >> 2, tg = lane & 3;

  float acc[4][4][4];
#pragma unroll
  for (int a = 0; a < 4; a++)
#pragma unroll
    for (int bb = 0; bb < 4; bb++)
#pragma unroll
      for (int cc = 0; cc < 4; cc++) acc[a][bb][cc] = 0.f;

  float4 ra[4], rb[4];

#define GRAM_LDG(KT)                                                         \
  do {                                                                       \
    _Pragma("unroll") for (int i = 0; i < 4; i++) {                          \
      int idx = tid + i * 256;                                               \
      int r = idx >> 3, c4 = idx & 7;                                        \
      int rowA = i0 + r;                                                     \
      if (rowA < ZROWS) {                                                    \
        const float* p = (rowA < CDIM) ? (xb + (size_t)rowA * HWDIM)         \
                                       : (qb + (size_t)(rowA - CDIM) * HWDIM); \
        ra[i] = *reinterpret_cast<const float4*>(p + (KT) + c4 * 4);         \
      } else ra[i] = make_float4(0.f, 0.f, 0.f, 0.f);                        \
      int rowB = j0 + r;                                                     \
      if (rowB < ZROWS) {                                                    \
        const float* p = (rowB < CDIM) ? (xb + (size_t)rowB * HWDIM)         \
                                       : (qb + (size_t)(rowB - CDIM) * HWDIM); \
        rb[i] = *reinterpret_cast<const float4*>(p + (KT) + c4 * 4);         \
      } else rb[i] = make_float4(0.f, 0.f, 0.f, 0.f);                        \
    }                                                                        \
  } while (0)

#define GRAM_STS(BUF)                                                        \
  do {                                                                       \
    _Pragma("unroll") for (int i = 0; i < 4; i++) {                          \
      int idx = tid + i * 256;                                               \
      int r = idx >> 3, c4 = idx & 7;                                        \
      uint32_t* pa = &As[(BUF)*128*36 + r * 36 + c4 * 4];                    \
      pa[0] = f2tf32(ra[i].x); pa[1] = f2tf32(ra[i].y);                      \
      pa[2] = f2tf32(ra[i].z); pa[3] = f2tf32(ra[i].w);                      \
      uint32_t* pb = &Bs[(BUF)*128*36 + r * 36 + c4 * 4];                    \
      pb[0] = f2tf32(rb[i].x); pb[1] = f2tf32(rb[i].y);                      \
      pb[2] = f2tf32(rb[i].z); pb[3] = f2tf32(rb[i].w);                      \
    }                                                                        \
  } while (0)

  GRAM_LDG(0);
  GRAM_STS(0);
  int cur = 0;
  const int NT = HWDIM / 32;
#pragma unroll 1
  for (int kt = 0; kt < NT; kt++) {
    __syncthreads();
    if (kt + 1 < NT) GRAM_LDG((kt + 1) * 32);
    const uint32_t* Ab = &As[cur * 128 * 36];
    const uint32_t* Bb = &Bs[cur * 128 * 36];
#pragma unroll
    for (int kk = 0; kk < 32; kk += 8) {
      uint32_t af[4][4], bf[4][2];
#pragma unroll
      for (int mf = 0; mf < 4; mf++) {
        int r = wm * 64 + mf * 16;
        af[mf][0] = Ab[(r + g) * 36 + kk + tg];
        af[mf][1] = Ab[(r + g + 8) * 36 + kk + tg];
        af[mf][2] = Ab[(r + g) * 36 + kk + tg + 4];
        af[mf][3] = Ab[(r + g + 8) * 36 + kk + tg + 4];
      }
#pragma unroll
      for (int nf = 0; nf < 4; nf++) {
        int rn = wn * 32 + nf * 8;
        bf[nf][0] = Bb[(rn + g) * 36 + kk + tg];
        bf[nf][1] = Bb[(rn + g) * 36 + kk + tg + 4];
      }
#pragma unroll
      for (int mf = 0; mf < 4; mf++)
#pragma unroll
        for (int nf = 0; nf < 4; nf++) mma_tf32(acc[mf][nf], af[mf], bf[nf]);
    }
    if (kt + 1 < NT) GRAM_STS(cur ^ 1);
    cur ^= 1;
  }

  float* Gb = G + (size_t)b * ZROWS * ZROWS;
#pragma unroll
  for (int mf = 0; mf < 4; mf++)
#pragma unroll
    for (int nf = 0; nf < 4; nf++) {
      int ib = i0 + wm * 64 + mf * 16 + g;
      int jb = j0 + wn * 32 + nf * 8 + 2 * tg;
#pragma unroll
      for (int e = 0; e < 4; e++) {
        int ii = ib + ((e >= 2) ? 8 : 0);
        int jj = jb + (e & 1);
        float v = acc[mf][nf][e];
        if (ii < ZROWS && jj < ZROWS) {
          Gb[(size_t)ii * ZROWS + jj] = v;
          Gb[(size_t)jj * ZROWS + ii] = v;
        }
      }
    }
#undef GRAM_LDG
#undef GRAM_STS
}

// =====================================================================
// kernel 2: big NN GEMM 128x128 tiles (final out = M @ X), double-buffered
// dims must tile exactly (here M=384,N=4096,K=384)
// dyn smem = (2*128*36 + 2*32*132)*4 = 70656 B
// =====================================================================
__global__ __launch_bounds__(256) void gemm_nn_tf32(
    const float* __restrict__ A, int lda, long long sA,
    const float* __restrict__ B, int ldb, long long sB, float* __restrict__ C,
    int ldc, long long sC, int K) {
  extern __shared__ uint32_t smg[];
  uint32_t* As = smg;                  // [2][128][36]
  uint32_t* Bs = smg + 2 * 128 * 36;   // [2][32][132]

  const int b = blockIdx.z;
  A += (size_t)b * sA;
  B += (size_t)b * sB;
  C += (size_t)b * sC;
  const int m0 = blockIdx.y * 128, n0 = blockIdx.x * 128;

  const int tid = threadIdx.x;
  const int lane = tid & 31, wid = tid >> 5;
  const int wm = wid & 1, wn = wid >> 1;
  const int g = lane >> 2, tg = lane & 3;

  float acc[4][4][4];
#pragma unroll
  for (int a = 0; a < 4; a++)
#pragma unroll
    for (int bb = 0; bb < 4; bb++)
#pragma unroll
      for (int cc = 0; cc < 4; cc++) acc[a][bb][cc] = 0.f;

  float4 ra[4], rb[4];

#define GEMM_LDG(KT)                                                          \
  do {                                                                        \
    _Pragma("unroll") for (int i = 0; i < 4; i++) {                           \
      int idx = tid + i * 256;                                                \
      { int r = idx >> 3, c4 = idx & 7;                                       \
        ra[i] = *reinterpret_cast<const float4*>(                             \
            A + (size_t)(m0 + r) * lda + (KT) + c4 * 4); }                    \
      { int r = idx >> 5, c4 = idx & 31;                                      \
        rb[i] = *reinterpret_cast<const float4*>(                             \
            B + (size_t)((KT) + r) * ldb + n0 + c4 * 4); }                    \
    }                                                                         \
  } while (0)

#define GEMM_STS(BUF)                                                         \
  do {                                                                        \
    _Pragma("unroll") for (int i = 0; i < 4; i++) {                           \
      int idx = tid + i * 256;                                                \
      { int r = idx >> 3, c4 = idx & 7;                                       \
        uint32_t* pa = &As[(BUF)*128*36 + r * 36 + c4 * 4];                   \
        pa[0] = f2tf32(ra[i].x); pa[1] = f2tf32(ra[i].y);                     \
        pa[2] = f2tf32(ra[i].z); pa[3] = f2tf32(ra[i].w); }                   \
      { int r = idx >> 5, c4 = idx & 31;                                      \
        uint32_t* pb = &Bs[(BUF)*32*132 + r * 132 + c4 * 4];                  \
        pb[0] = f2tf32(rb[i].x); pb[1] = f2tf32(rb[i].y);                     \
        pb[2] = f2tf32(rb[i].z); pb[3] = f2tf32(rb[i].w); }                   \
    }                                                                         \
  } while (0)

  GEMM_LDG(0);
  GEMM_STS(0);
  int cur = 0;
  const int NT = K / 32;
#pragma unroll 1
  for (int kt = 0; kt < NT; kt++) {
    __syncthreads();
    if (kt + 1 < NT) GEMM_LDG((kt + 1) * 32);
    const uint32_t* Ab = &As[cur * 128 * 36];
    const uint32_t* Bb = &Bs[cur * 32 * 132];
#pragma unroll
    for (int kk = 0; kk < 32; kk += 8) {
      uint32_t af[4][4], bf[4][2];
#pragma unroll
      for (int mf = 0; mf < 4; mf++) {
        int r = wm * 64 + mf * 16;
        af[mf][0] = Ab[(r + g) * 36 + kk + tg];
        af[mf][1] = Ab[(r + g + 8) * 36 + kk + tg];
        af[mf][2] = Ab[(r + g) * 36 + kk + tg + 4];
        af[mf][3] = Ab[(r + g + 8) * 36 + kk + tg + 4];
      }
#pragma unroll
      for (int nf = 0; nf < 4; nf++) {
        int cn = wn * 32 + nf * 8 + g;
        bf[nf][0] = Bb[(kk + tg) * 132 + cn];
        bf[nf][1] = Bb[(kk + tg + 4) * 132 + cn];
      }
#pragma unroll
      for (int mf = 0; mf < 4; mf++)
#pragma unroll
        for (int nf = 0; nf < 4; nf++) mma_tf32(acc[mf][nf], af[mf], bf[nf]);
    }
    if (kt + 1 < NT) GEMM_STS(cur ^ 1);
    cur ^= 1;
  }

#pragma unroll
  for (int mf = 0; mf < 4; mf++)
#pragma unroll
    for (int nf = 0; nf < 4; nf++) {
      int ib = m0 + wm * 64 + mf * 16 + g;
      int jb = n0 + wn * 32 + nf * 8 + 2 * tg;
#pragma unroll
      for (int e = 0; e < 4; e++) {
        int ii = ib + ((e >= 2) ? 8 : 0);
        int jj = jb + (e & 1);
        C[(size_t)ii * ldc + jj] = acc[mf][nf][e];
      }
    }
#undef GEMM_LDG
#undef GEMM_STS
}

// =====================================================================
// 64x64-tile tf32 GEMM device fn (block = 128 threads), double-buffered.
// =====================================================================
__device__ __forceinline__ void gemm64_tf32(const float* __restrict__ A,
                                            int lda, const float* __restrict__ B,
                                            int ldb, float* __restrict__ C,
                                            int ldc, int m0, int n0, int K) {
  __shared__ uint32_t As[2 * 64 * 36];
  __shared__ uint32_t Bs[2 * 32 * 68];

  const int tid = threadIdx.x;
  const int lane = tid & 31, wid = tid >> 5;
  const int wm = wid & 1, wn = wid >> 1;  // 2x2 warp grid
  const int g = lane >> 2, tg = lane & 3;

  float acc[2][4][4];
#pragma unroll
  for (int a = 0; a < 2; a++)
#pragma unroll
    for (int bb = 0; bb < 4; bb++)
#pragma unroll
      for (int cc = 0; cc < 4; cc++) acc[a][bb][cc] = 0.f;

  float4 ra[4], rb[4];

#define G64_LDG(KT)                                                           \
  do {                                                                        \
    _Pragma("unroll") for (int i = 0; i < 4; i++) {                           \
      int idx = tid + i * 128;                                                \
      { int r = idx >> 3, c4 = idx & 7;                                       \
        ra[i] = *reinterpret_cast<const float4*>(                             \
            A + (size_t)(m0 + r) * lda + (KT) + c4 * 4); }                    \
      { int r = idx >> 4, c4 = idx & 15;                                      \
        rb[i] = *reinterpret_cast<const float4*>(                             \
            B + (size_t)((KT) + r) * ldb + n0 + c4 * 4); }                    \
    }                                                                         \
  } while (0)

#define G64_STS(BUF)                                                          \
  do {                                                                        \
    _Pragma("unroll") for (int i = 0; i < 4; i++) {                           \
      int idx = tid + i * 128;                                                \
      { int r = idx >> 3, c4 = idx & 7;                                       \
        uint32_t* pa = &As[(BUF)*64*36 + r * 36 + c4 * 4];                    \
        pa[0] = f2tf32(ra[i].x); pa[1] = f2tf32(ra[i].y);                     \
        pa[2] = f2tf32(ra[i].z); pa[3] = f2tf32(ra[i].w); }                   \
      { int r = idx >> 4, c4 = idx & 15;                                      \
        uint32_t* pb = &Bs[(BUF)*32*68 + r * 68 + c4 * 4];                    \
        pb[0] = f2tf32(rb[i].x); pb[1] = f2tf32(rb[i].y);                     \
        pb[2] = f2tf32(rb[i].z); pb[3] = f2tf32(rb[i].w); }                   \
    }                                                                         \
  } while (0)

  G64_LDG(0);
  G64_STS(0);
  int cur = 0;
  const int NT = K / 32;
#pragma unroll 1
  for (int kt = 0; kt < NT; kt++) {
    __syncthreads();
    if (kt + 1 < NT) G64_LDG((kt + 1) * 32);
    const uint32_t* Ab = &As[cur * 64 * 36];
    const uint32_t* Bb = &Bs[cur * 32 * 68];
#pragma unroll
    for (int kk = 0; kk < 32; kk += 8) {
      uint32_t af[2][4], bf[4][2];
#pragma unroll
      for (int mf = 0; mf < 2; mf++) {
        int r = wm * 32 + mf * 16;
        af[mf][0] = Ab[(r + g) * 36 + kk + tg];
        af[mf][1] = Ab[(r + g + 8) * 36 + kk + tg];
        af[mf][2] = Ab[(r + g) * 36 + kk + tg + 4];
        af[mf][3] = Ab[(r + g + 8) * 36 + kk + tg + 4];
      }
#pragma unroll
      for (int nf = 0; nf < 4; nf++) {
        int cn = wn * 32 + nf * 8 + g;
        bf[nf][0] = Bb[(kk + tg) * 68 + cn];
        bf[nf][1] = Bb[(kk + tg + 4) * 68 + cn];
      }
#pragma unroll
      for (int mf = 0; mf < 2; mf++)
#pragma unroll
        for (int nf = 0; nf < 4; nf++) mma_tf32(acc[mf][nf], af[mf], bf[nf]);
    }
    if (kt + 1 < NT) G64_STS(cur ^ 1);
    cur ^= 1;
  }

#pragma unroll
  for (int mf = 0; mf < 2; mf++)
#pragma unroll
    for (int nf = 0; nf < 4; nf++) {
      int ib = m0 + wm * 32 + mf * 16 + g;
      int jb = n0 + wn * 32 + nf * 8 + 2 * tg;
#pragma unroll
      for (int e = 0; e < 4; e++) {
        int ii = ib + ((e >= 2) ? 8 : 0);
        int jj = jb + (e & 1);
        C[(size_t)ii * ldc + jj] = acc[mf][nf][e];
      }
    }
#undef G64_LDG
#undef G64_STS
}

// kernel 3: fused T1/V1/T2 — grid (90, 16), block 128
__global__ __launch_bounds__(128) void mid3_kernel(
    const float* __restrict__ w_kv, const float* __restrict__ w_q,
    const float* __restrict__ G, float* __restrict__ T1,
    float* __restrict__ V1, float* __restrict__ T2) {
  int t = blockIdx.x;
  const int b = blockIdx.y;
  const float* Gb = G + (size_t)b * ZROWS * ZROWS;
  if (t < 36) {
    int tm = t / 6, tn = t % 6;
    gemm64_tf32(w_kv, CDIM, Gb, ZROWS, T1 + (size_t)b * CDIM * CDIM, CDIM,
                tm * 64, tn * 64, CDIM);
  } else if (t < 72) {
    t -= 36;
    int tm = t / 6, tn = t % 6;
    gemm64_tf32(w_q, QCDIM, Gb + (size_t)CDIM * ZROWS, ZROWS,
                V1 + (size_t)b * CDIM * CDIM, CDIM, tm * 64, tn * 64, QCDIM);
  } else {
    t -= 72;
    int tm = t / 3, tn = t % 3;
    gemm64_tf32(w_q, QCDIM, Gb + (size_t)CDIM * ZROWS + CDIM, ZROWS,
                T2 + (size_t)b * CDIM * QCDIM, QCDIM, tm * 64, tn * 64, QCDIM);
  }
}

// kernel 5: M = W_proj @ Av — grid (36, 16), block 128
__global__ __launch_bounds__(128) void proj_kernel(
    const float* __restrict__ w_proj, const float* __restrict__ Av,
    float* __restrict__ M) {
  const int t = blockIdx.x, b = blockIdx.y;
  int tm = t / 6, tn = t % 6;
  gemm64_tf32(w_proj, CDIM, Av + (size_t)b * CDIM * CDIM,
              CDIM, M + (size_t)b * CDIM * CDIM, CDIM, tm * 64, tn * 64, CDIM);
}

// =====================================================================
// kernel 4: norms + logits + softmax + Av, grid (8, 16), block 256
// dyn smem = 2*48*388*4 = 148992 B
// =====================================================================
__global__ __launch_bounds__(256) void attn_kernel(
    const float* __restrict__ V1, const float* __restrict__ w_kv,
    const float* __restrict__ w_q, const float* __restrict__ T1,
    const float* __restrict__ T2, const float* __restrict__ temperature,
    float* __restrict__ Av) {
  const int h = blockIdx.x;
  const int b = blockIdx.y;
  extern __shared__ float sm[];
  float* V1h = sm;             // [48][388]
  float* Wh = sm + 48 * 388;   // [48][388]
  __shared__ float Ssm[DCH][DCH + 1];
  __shared__ float St[DCH][52];  // transposed attn (d-major)
  __shared__ float invk_s[DCH], invq_s[DCH];

  const int tid = threadIdx.x;
  const int lane = tid & 31, wid = tid >> 5;

  // load V1 head rows + Wk head rows into smem (float4)
  for (int idx = tid; idx < DCH * (CDIM / 4); idx += 256) {
    int c = idx / (CDIM / 4), k4 = idx % (CDIM / 4);
    float4 v = reinterpret_cast<const float4*>(
        V1 + ((size_t)b * CDIM + h * DCH + c) * CDIM)[k4];
    *reinterpret_cast<float4*>(&V1h[c * 388 + k4 * 4]) = v;
    float4 w = reinterpret_cast<const float4*>(
        w_kv + (size_t)(h * DCH + c) * CDIM)[k4];
    *reinterpret_cast<float4*>(&Wh[c * 388 + k4 * 4]) = w;
  }

  // norms: invk[r] from T1 row . Wk row;  invq[r] from T2 row . Wq row
  for (int r = wid; r < DCH; r += 8) {
    const float4* t1 = reinterpret_cast<const float4*>(
        T1 + ((size_t)b * CDIM + h * DCH + r) * CDIM);
    const float4* wk = reinterpret_cast<const float4*>(
        w_kv + (size_t)(h * DCH + r) * CDIM);
    float s = 0.f;
    for (int i = lane; i < CDIM / 4; i += 32) {
      float4 a = t1[i], w = wk[i];
      s += a.x * w.x + a.y * w.y + a.z * w.z + a.w * w.w;
    }
#pragma unroll
    for (int off = 16; off; off >>= 1) s += __shfl_xor_sync(0xFFFFFFFFu, s, off);
    if (lane == 0)
      invk_s[r] = 1.f / fmaxf(sqrtf(fmaxf(s, 0.f)), 1e-12f);

    const float4* t2 = reinterpret_cast<const float4*>(
        T2 + ((size_t)b * CDIM + h * DCH + r) * QCDIM);
    const float4* wq = reinterpret_cast<const float4*>(
        w_q + (size_t)(h * DCH + r) * QCDIM);
    float s2 = 0.f;
    for (int i = lane; i < QCDIM / 4; i += 32) {
      float4 a = t2[i], w = wq[i];
      s2 += a.x * w.x + a.y * w.y + a.z * w.z + a.w * w.w;
    }
#pragma unroll
    for (int off = 16; off; off >>= 1) s2 += __shfl_xor_sync(0xFFFFFFFFu, s2, off);
    if (lane == 0)
      invq_s[r] = 1.f / fmaxf(sqrtf(fmaxf(s2, 0.f)), 1e-12f);
  }
  __syncthreads();

  // logits: 3x3 register tile per thread (256 threads cover 48x48)
  const float temp = temperature[h];
  {
    const int c0 = (tid >> 4) * 3, d0 = (tid & 15) * 3;
    float s[3][3] = {{0.f, 0.f, 0.f}, {0.f, 0.f, 0.f}, {0.f, 0.f, 0.f}};
    for (int k = 0; k < CDIM; k += 4) {
      float4 a0 = *reinterpret_cast<const float4*>(&V1h[(c0 + 0) * 388 + k]);
      float4 a1 = *reinterpret_cast<const float4*>(&V1h[(c0 + 1) * 388 + k]);
      float4 a2 = *reinterpret_cast<const float4*>(&V1h[(c0 + 2) * 388 + k]);
      float4 w0 = *reinterpret_cast<const float4*>(&Wh[(d0 + 0) * 388 + k]);
      float4 w1 = *reinterpret_cast<const float4*>(&Wh[(d0 + 1) * 388 + k]);
      float4 w2 = *reinterpret_cast<const float4*>(&Wh[(d0 + 2) * 388 + k]);
#define DOT4(P, Q) (P.x * Q.x + P.y * Q.y + P.z * Q.z + P.w * Q.w)
      s[0][0] += DOT4(a0, w0); s[0][1] += DOT4(a0, w1); s[0][2] += DOT4(a0, w2);
      s[1][0] += DOT4(a1, w0); s[1][1] += DOT4(a1, w1); s[1][2] += DOT4(a1, w2);
      s[2][0] += DOT4(a2, w0); s[2][1] += DOT4(a2, w1); s[2][2] += DOT4(a2, w2);
#undef DOT4
    }
#pragma unroll
    for (int i = 0; i < 3; i++)
#pragma unroll
      for (int j = 0; j < 3; j++)
        Ssm[c0 + i][d0 + j] = s[i][j] * invq_s[c0 + i] * invk_s[d0 + j] * temp;
  }
  __syncthreads();

  // softmax over d per row c; write transposed into St[d][c]
  for (int c = wid; c < DCH; c += 8) {
    float a1 = Ssm[c][lane < DCH ? lane : 0];
    float a2 = (lane < DCH - 32) ? Ssm[c][lane + 32] : -1e30f;
    if (lane >= DCH) a1 = -1e30f;
    float m = fmaxf(a1, a2);
#pragma unroll
    for (int off = 16; off; off >>= 1)
      m = fmaxf(m, __shfl_xor_sync(0xFFFFFFFFu, m, off));
    float e1 = (lane < DCH) ? expf(a1 - m) : 0.f;
    float e2 = (lane < DCH - 32) ? expf(a2 - m) : 0.f;
    float su = e1 + e2;
#pragma unroll
    for (int off = 16; off; off >>= 1) su += __shfl_xor_sync(0xFFFFFFFFu, su, off);
    float inv = 1.f / su;
    if (lane < DCH) St[lane][c] = e1 * inv;
    if (lane < DCH - 32) St[lane + 32][c] = e2 * inv;
  }
  __syncthreads();

  // load Wv head rows into Wh (overwrites Wk)
  for (int idx = tid; idx < DCH * (CDIM / 4); idx += 256) {
    int d = idx / (CDIM / 4), k4 = idx % (CDIM / 4);
    float4 w = reinterpret_cast<const float4*>(
        w_kv + (size_t)(CDIM + h * DCH + d) * CDIM)[k4];
    *reinterpret_cast<float4*>(&Wh[d * 388 + k4 * 4]) = w;
  }
  __syncthreads();

  // Av = attn @ Wv, 4x4 register tiles (tiles: 12 c-tiles x 96 j-tiles)
  for (int tt = tid; tt < 12 * 96; tt += 256) {
    int c0 = (tt / 96) * 4, j0 = (tt % 96) * 4;
    float f00 = 0, f01 = 0, f02 = 0, f03 = 0, f10 = 0, f11 = 0, f12 = 0,
          f13 = 0, f20 = 0, f21 = 0, f22 = 0, f23 = 0, f30 = 0, f31 = 0,
          f32 = 0, f33 = 0;
#pragma unroll 8
    for (int d = 0; d < DCH; d++) {
      float4 sv = *reinterpret_cast<const float4*>(&St[d][c0]);
      float4 wv = *reinterpret_cast<const float4*>(&Wh[d * 388 + j0]);
      f00 += sv.x * wv.x; f01 += sv.x * wv.y; f02 += sv.x * wv.z; f03 += sv.x * wv.w;
      f10 += sv.y * wv.x; f11 += sv.y * wv.y; f12 += sv.y * wv.z; f13 += sv.y * wv.w;
      f20 += sv.z * wv.x; f21 += sv.z * wv.y; f22 += sv.z * wv.z; f23 += sv.z * wv.w;
      f30 += sv.w * wv.x; f31 += sv.w * wv.y; f32 += sv.w * wv.z; f33 += sv.w * wv.w;
    }
    float* o = Av + ((size_t)b * CDIM + h * DCH + c0) * CDIM + j0;
    *reinterpret_cast<float4*>(o) = make_float4(f00, f01, f02, f03);
    *reinterpret_cast<float4*>(o + CDIM) = make_float4(f10, f11, f12, f13);
    *reinterpret_cast<float4*>(o + 2 * CDIM) = make_float4(f20, f21, f22, f23);
    *reinterpret_cast<float4*>(o + 3 * CDIM) = make_float4(f30, f31, f32, f33);
  }
}

// ---------------- host ----------------
extern "C" void kernel_launch(void* const* d_in, const int* in_sizes, int n_in,
                              void* d_out, int out_size) {
  (void)in_sizes; (void)n_in; (void)out_size;
  const float* x = (const float*)d_in[0];
  const float* query = (const float*)d_in[1];
  const float* w_kv = (const float*)d_in[2];
  const float* w_q = (const float*)d_in[3];
  const float* w_proj = (const float*)d_in[4];
  const float* temp = (const float*)d_in[5];
  float* out = (float*)d_out;

  float *G, *T1, *V1, *T2, *Av, *M;
  cudaGetSymbolAddress((void**)&G, g_G);
  cudaGetSymbolAddress((void**)&T1, g_T1);
  cudaGetSymbolAddress((void**)&V1, g_V1);
  cudaGetSymbolAddress((void**)&T2, g_T2);
  cudaGetSymbolAddress((void**)&Av, g_Av);
  cudaGetSymbolAddress((void**)&M, g_M);

  const int gram_smem = 2 * 128 * 36 * 2 * 4;               // 73728
  const int gemm_smem = (2 * 128 * 36 + 2 * 32 * 132) * 4;  // 70656
  const int attn_smem = 2 * 48 * 388 * 4;                   // 148992
  cudaFuncSetAttribute(gram_nt_kernel,
                       cudaFuncAttributeMaxDynamicSharedMemorySize, gram_smem);
  cudaFuncSetAttribute(gemm_nn_tf32,
                       cudaFuncAttributeMaxDynamicSharedMemorySize, gemm_smem);
  cudaFuncSetAttribute(attn_kernel,
                       cudaFuncAttributeMaxDynamicSharedMemorySize, attn_smem);

  // 1) Gram
  gram_nt_kernel<<<dim3(15, BATCH), 256, gram_smem>>>(x, query, G);
  // 2) T1 / V1 / T2 fused
  mid3_kernel<<<dim3(90, BATCH), 128>>>(w_kv, w_q, G, T1, V1, T2);
  // 3) norms + logits + softmax + Av
  attn_kernel<<<dim3(HEADS, BATCH), 256, attn_smem>>>(V1, w_kv, w_q, T1, T2,
                                                      temp, Av);
  // 4) M = W_proj @ Av
  proj_kernel<<<dim3(36, BATCH), 128>>>(w_proj, Av, M);
  // 5) out = M @ X
  gemm_nn_tf32<<<dim3(32, 3, BATCH), 256, gemm_smem>>>(
      M, CDIM, (long long)CDIM * CDIM, x, HWDIM, (long long)CDIM * HWDIM, out,
      HWDIM, (long long)CDIM * HWDIM, CDIM);
}